// round 16
// baseline (speedup 1.0000x reference)
#include <cuda_runtime.h>
#include <cuda_fp16.h>
#include <math.h>
#include <stdint.h>

// Problem constants
#define Bb   4
#define Tt   1024
#define Cc   1024
#define Hh   16
#define Dd   64
#define Ee   8
#define BOTd 64
#define Mrows 4096           // B*T
#define CH    4096           // 4*C
#define C3   3072            // 3*C
#define TPB  16              // tokens per adapter block

// ---------------- scratch (device globals; no allocation allowed) -----------
__device__ __half g_h  [Mrows*Cc];
__device__ __half g_qkv[Mrows*C3];
__device__ __half g_y  [Mrows*Cc];
__device__ float  g_x1 [Mrows*Cc];
__device__ float  g_yad0[Mrows*Cc];
__device__ float  g_yad1[Mrows*Cc];
__device__ __half g_h2 [Mrows*Cc];
__device__ __half g_mid[Mrows*CH];
__device__ float  g_bqkv[C3];
// MoE dispatch lists
__device__ int   g_cnt[16];
__device__ int   g_listA[2*Ee*Tt];
__device__ float g_glA [2*Ee*Tt];
// transposed weights, fp16 (K-major B operands: Wt[N][K])
__device__ __half g_wqkvt[C3*Cc];
__device__ __half g_wot[Cc*Cc];
__device__ __half g_w1t[Cc*CH];
__device__ __half g_w2t[CH*Cc];

__device__ __forceinline__ uint32_t s2u(const void* p) {
    return (uint32_t)__cvta_generic_to_shared(p);
}

// ---------------- bias concat: bqkv = [bq | bk | bv] -------------------------
__global__ __launch_bounds__(256)
void concat_bias(const float* __restrict__ bq, const float* __restrict__ bk,
                 const float* __restrict__ bv, float* __restrict__ out)
{
    int b = blockIdx.x;
    const float* src = (b == 0) ? bq : (b == 1) ? bk : bv;
    int i = threadIdx.x * 4;
    *(float4*)(out + b * Cc + i) = *(const float4*)(src + i);
}

// ---------------- FP16 mma.sync GEMM v4: 3-stage cp.async pipeline -----------
#define SH 40                        // smem row stride in halves (80B)
#define STG 3                        // pipeline stages
#define SMEM_GEMM (STG * 128 * SH * 2 * 2)   // 61440 bytes

template<int EPI, typename OutT>
__global__ __launch_bounds__(256, 2)
void mma_gemm(const __half* __restrict__ A, const __half* __restrict__ Wt,
              const float* __restrict__ bias, const float* __restrict__ R1,
              const float* __restrict__ R2, const float* __restrict__ R3,
              OutT* __restrict__ O, int Md, int Nd, int Kd)
{
    extern __shared__ __half smdyn[];
    __half* Ab = smdyn;                        // STG * 128*SH
    __half* Bb2 = smdyn + STG * 128 * SH;
    int tid = threadIdx.x, wid = tid >> 5, lane = tid & 31;
    int wm = wid & 3, wn = wid >> 2;
    int n0 = blockIdx.x * 128, m0 = blockIdx.y * 128;

    float d[2][8][4];
    #pragma unroll
    for (int mt = 0; mt < 2; mt++)
        #pragma unroll
        for (int nt = 0; nt < 8; nt++)
            #pragma unroll
            for (int r = 0; r < 4; r++) d[mt][nt][r] = 0.f;

    int laneRowA = (lane & 7) + ((lane >> 3) & 1) * 8;
    int laneColA = (lane >> 4) * 8;
    int laneRowB = (lane & 7) + (lane >> 4) * 8;
    int laneColB = ((lane >> 3) & 1) * 8;

    uint32_t asb[STG], bsb[STG];
    #pragma unroll
    for (int s = 0; s < STG; s++) {
        asb[s] = s2u(Ab  + s * 128 * SH);
        bsb[s] = s2u(Bb2 + s * 128 * SH);
    }

    const int NC = Kd >> 5;
    int ldrow = tid >> 2, ldc8 = (tid & 3) << 3;   // 64 rows x 4 col-groups; x4 rows via +64

    // prologue: issue copies for chunks 0 and 1 into stages 0,1
    #pragma unroll
    for (int pc = 0; pc < 2; pc++) {
        int k0 = pc << 5;
        #pragma unroll
        for (int l = 0; l < 2; l++) {
            int row = ldrow + (l << 6);
            uint32_t da = asb[pc] + ((row * SH + ldc8) << 1);
            const __half* sa = A + (size_t)(m0 + row) * Kd + k0 + ldc8;
            asm volatile("cp.async.cg.shared.global [%0], [%1], 16;" :: "r"(da), "l"(sa));
            uint32_t db = bsb[pc] + ((row * SH + ldc8) << 1);
            const __half* sb = Wt + (size_t)(n0 + row) * Kd + k0 + ldc8;
            asm volatile("cp.async.cg.shared.global [%0], [%1], 16;" :: "r"(db), "l"(sb));
        }
        asm volatile("cp.async.commit_group;");
    }

    int cur = 0, nxt2 = 2;   // stage of chunk i, stage for chunk i+2
    for (int i = 0; i < NC; i++) {
        if (i + 1 < NC) asm volatile("cp.async.wait_group 1;");
        else            asm volatile("cp.async.wait_group 0;");
        __syncthreads();
        if (i + 2 < NC) {
            int k0 = (i + 2) << 5;
            #pragma unroll
            for (int l = 0; l < 2; l++) {
                int row = ldrow + (l << 6);
                uint32_t da = asb[nxt2] + ((row * SH + ldc8) << 1);
                const __half* sa = A + (size_t)(m0 + row) * Kd + k0 + ldc8;
                asm volatile("cp.async.cg.shared.global [%0], [%1], 16;" :: "r"(da), "l"(sa));
                uint32_t db = bsb[nxt2] + ((row * SH + ldc8) << 1);
                const __half* sb = Wt + (size_t)(n0 + row) * Kd + k0 + ldc8;
                asm volatile("cp.async.cg.shared.global [%0], [%1], 16;" :: "r"(db), "l"(sb));
            }
            asm volatile("cp.async.commit_group;");
        }
        // compute chunk i from stage cur
        #pragma unroll
        for (int kk = 0; kk < 2; kk++) {
            int kc = kk << 4;
            uint32_t a[2][4];
            #pragma unroll
            for (int mt = 0; mt < 2; mt++) {
                uint32_t addr = asb[cur] +
                    (((wm * 32 + mt * 16 + laneRowA) * SH + kc + laneColA) << 1);
                asm volatile(
                    "ldmatrix.sync.aligned.m8n8.x4.shared.b16 {%0,%1,%2,%3}, [%4];"
                    : "=r"(a[mt][0]), "=r"(a[mt][1]), "=r"(a[mt][2]), "=r"(a[mt][3])
                    : "r"(addr));
            }
            #pragma unroll
            for (int ntp = 0; ntp < 4; ntp++) {
                uint32_t bb[4];
                uint32_t addr = bsb[cur] +
                    (((wn * 64 + ntp * 16 + laneRowB) * SH + kc + laneColB) << 1);
                asm volatile(
                    "ldmatrix.sync.aligned.m8n8.x4.shared.b16 {%0,%1,%2,%3}, [%4];"
                    : "=r"(bb[0]), "=r"(bb[1]), "=r"(bb[2]), "=r"(bb[3])
                    : "r"(addr));
                #pragma unroll
                for (int hf = 0; hf < 2; hf++) {
                    int nt = ntp * 2 + hf;
                    #pragma unroll
                    for (int mt = 0; mt < 2; mt++) {
                        asm volatile(
                            "mma.sync.aligned.m16n8k16.row.col.f32.f16.f16.f32 "
                            "{%0,%1,%2,%3}, {%4,%5,%6,%7}, {%8,%9}, {%0,%1,%2,%3};"
                            : "+f"(d[mt][nt][0]), "+f"(d[mt][nt][1]),
                              "+f"(d[mt][nt][2]), "+f"(d[mt][nt][3])
                            : "r"(a[mt][0]), "r"(a[mt][1]), "r"(a[mt][2]), "r"(a[mt][3]),
                              "r"(bb[hf * 2]), "r"(bb[hf * 2 + 1]));
                    }
                }
            }
        }
        cur = (cur + 1 == STG) ? 0 : cur + 1;
        nxt2 = (nxt2 + 1 == STG) ? 0 : nxt2 + 1;
    }

    int g = lane >> 2, t2 = (lane & 3) * 2;
    #pragma unroll
    for (int mt = 0; mt < 2; mt++) {
        int r0 = m0 + wm * 32 + mt * 16 + g;
        #pragma unroll
        for (int nt = 0; nt < 8; nt++) {
            int c = n0 + wn * 64 + nt * 8 + t2;
            float bx = bias[c], by = bias[c + 1];
            #pragma unroll
            for (int hrow = 0; hrow < 2; hrow++) {
                int r = r0 + hrow * 8;
                size_t base = (size_t)r * Nd + c;
                float vx = d[mt][nt][hrow * 2]     + bx;
                float vy = d[mt][nt][hrow * 2 + 1] + by;
                if (EPI == 1) {
                    float2 r1 = *(const float2*)(R1 + base);
                    vx += r1.x; vy += r1.y;
                }
                if (EPI == 2) {
                    vx = 0.5f * vx * (1.f + erff(vx * 0.70710678118654752f));
                    vy = 0.5f * vy * (1.f + erff(vy * 0.70710678118654752f));
                }
                if (EPI == 3) {
                    float2 r1 = *(const float2*)(R1 + base);
                    float2 r2 = *(const float2*)(R2 + base);
                    float2 r3 = *(const float2*)(R3 + base);
                    vx += r1.x + r2.x + r3.x; vy += r1.y + r2.y + r3.y;
                }
                if constexpr (sizeof(OutT) == 2) {
                    __half2 hv = __floats2half2_rn(vx, vy);
                    *(__half2*)((__half*)O + base) = hv;
                } else {
                    *(float2*)((float*)O + base) = make_float2(vx, vy);
                }
            }
        }
    }
}

// ------------- weight transpose+convert: in[K][N] f32 -> out[N][K] f16 -------
__global__ __launch_bounds__(256)
void transpose_k(const float* __restrict__ in, __half* __restrict__ out,
                 int K, int N)
{
    __shared__ float t[32][33];
    int kb = blockIdx.y * 32, nb = blockIdx.x * 32;
    int x = threadIdx.x, y = threadIdx.y;   // 32 x 8
    #pragma unroll
    for (int dy = 0; dy < 32; dy += 8)
        t[y + dy][x] = in[(size_t)(kb + y + dy) * N + nb + x];
    __syncthreads();
    #pragma unroll
    for (int dy = 0; dy < 32; dy += 8)
        out[(size_t)(nb + y + dy) * K + kb + x] = __float2half(t[x][y + dy]);
}

// ---------------- LayerNorm: fused sum/sumsq, shfl reduction -----------------
__global__ __launch_bounds__(256)
void ln_k(const float* __restrict__ X, const float* __restrict__ G,
          const float* __restrict__ Bt, __half* __restrict__ O)
{
    __shared__ float sm1[8], sm2[8], bcast[2];
    int row = blockIdx.x, tid = threadIdx.x;
    int wid = tid >> 5, lane = tid & 31;
    const float* xr = X + (size_t)row * Cc;
    float4 xv = *(const float4*)(xr + tid * 4);
    float s1 = xv.x + xv.y + xv.z + xv.w;
    float s2 = xv.x*xv.x + xv.y*xv.y + xv.z*xv.z + xv.w*xv.w;
    #pragma unroll
    for (int off = 16; off > 0; off >>= 1) {
        s1 += __shfl_down_sync(0xffffffffu, s1, off);
        s2 += __shfl_down_sync(0xffffffffu, s2, off);
    }
    if (lane == 0) { sm1[wid] = s1; sm2[wid] = s2; }
    __syncthreads();
    if (wid == 0) {
        float t1 = (lane < 8) ? sm1[lane] : 0.f;
        float t2 = (lane < 8) ? sm2[lane] : 0.f;
        #pragma unroll
        for (int off = 4; off > 0; off >>= 1) {
            t1 += __shfl_down_sync(0xffffffffu, t1, off);
            t2 += __shfl_down_sync(0xffffffffu, t2, off);
        }
        if (lane == 0) {
            float mu = t1 * (1.f / 1024.f);
            float var = t2 * (1.f / 1024.f) - mu * mu;
            bcast[0] = mu;
            bcast[1] = rsqrtf(var + 1e-5f);
        }
    }
    __syncthreads();
    float mu = bcast[0], rs = bcast[1];
    float4 gv = *(const float4*)(G  + tid * 4);
    float4 bv = *(const float4*)(Bt + tid * 4);
    __half2 o0 = __floats2half2_rn((xv.x - mu)*rs*gv.x + bv.x,
                                   (xv.y - mu)*rs*gv.y + bv.y);
    __half2 o1 = __floats2half2_rn((xv.z - mu)*rs*gv.z + bv.z,
                                   (xv.w - mu)*rs*gv.w + bv.w);
    uint2 pk; pk.x = *(uint32_t*)&o0; pk.y = *(uint32_t*)&o1;
    *(uint2*)(O + (size_t)row * Cc + tid * 4) = pk;
}

// ---------------- FP16 tensor-core causal flash attention --------------------
#define AS 72
__global__ __launch_bounds__(128)
void attn_mma(const __half* __restrict__ QKV, __half* __restrict__ Y)
{
    __shared__ __half Ks[64 * AS];
    __shared__ __half Vs[64 * AS];
    int bh = blockIdx.y;
    int b = bh >> 4, h = bh & 15;
    int bx = blockIdx.x;
    int q0 = bx * 64;
    int tid = threadIdx.x, wid = tid >> 5, lane = tid & 31;
    int g = lane >> 2, t2 = (lane & 3) << 1;
    int r0l = wid * 16;

    const __half2 qscale = __floats2half2_rn(0.125f, 0.125f);

    #pragma unroll
    for (int i = 0; i < 4; i++) {
        int f = tid + (i << 7);
        int row = f >> 3, c8 = (f & 7) << 3;
        uint4 v4 = *(const uint4*)(QKV + ((size_t)(b * Tt + q0 + row)) * C3 + h * Dd + c8);
        __half2* hp = (__half2*)&v4;
        hp[0] = __hmul2(hp[0], qscale); hp[1] = __hmul2(hp[1], qscale);
        hp[2] = __hmul2(hp[2], qscale); hp[3] = __hmul2(hp[3], qscale);
        *(uint4*)&Ks[row * AS + c8] = v4;
    }
    __syncthreads();
    uint32_t qf[4][4];
    #pragma unroll
    for (int kk = 0; kk < 4; kk++) {
        qf[kk][0] = *(const uint32_t*)&Ks[(r0l + g) * AS + kk * 16 + t2];
        qf[kk][1] = *(const uint32_t*)&Ks[(r0l + g + 8) * AS + kk * 16 + t2];
        qf[kk][2] = *(const uint32_t*)&Ks[(r0l + g) * AS + kk * 16 + 8 + t2];
        qf[kk][3] = *(const uint32_t*)&Ks[(r0l + g + 8) * AS + kk * 16 + 8 + t2];
    }
    __syncthreads();

    int laneRowV = (lane & 7) + ((lane >> 3) & 1) * 8;
    int laneColV = (lane >> 4) * 8;
    uint32_t vsb = s2u(Vs);

    float m_lo = -1e30f, m_hi = -1e30f, l_lo = 0.f, l_hi = 0.f;
    float o[8][4];
    #pragma unroll
    for (int nt = 0; nt < 8; nt++)
        #pragma unroll
        for (int r = 0; r < 4; r++) o[nt][r] = 0.f;

    for (int it = 0; it <= bx; it++) {
        int s0 = it * 64;
        #pragma unroll
        for (int i = 0; i < 4; i++) {
            int f = tid + (i << 7);
            int row = f >> 3, c8 = (f & 7) << 3;
            size_t rb = ((size_t)(b * Tt + s0 + row)) * C3 + h * Dd + c8;
            *(uint4*)&Ks[row * AS + c8] = *(const uint4*)(QKV + Cc + rb);
            *(uint4*)&Vs[row * AS + c8] = *(const uint4*)(QKV + 2 * Cc + rb);
        }
        __syncthreads();

        float s[8][4];
        #pragma unroll
        for (int nt = 0; nt < 8; nt++) {
            #pragma unroll
            for (int r = 0; r < 4; r++) s[nt][r] = 0.f;
            int n = nt * 8 + g;
            #pragma unroll
            for (int kk = 0; kk < 4; kk++) {
                uint32_t b0 = *(const uint32_t*)&Ks[n * AS + kk * 16 + t2];
                uint32_t b1 = *(const uint32_t*)&Ks[n * AS + kk * 16 + 8 + t2];
                asm volatile(
                    "mma.sync.aligned.m16n8k16.row.col.f32.f16.f16.f32 "
                    "{%0,%1,%2,%3}, {%4,%5,%6,%7}, {%8,%9}, {%0,%1,%2,%3};"
                    : "+f"(s[nt][0]), "+f"(s[nt][1]), "+f"(s[nt][2]), "+f"(s[nt][3])
                    : "r"(qf[kk][0]), "r"(qf[kk][1]), "r"(qf[kk][2]), "r"(qf[kk][3]),
                      "r"(b0), "r"(b1));
            }
        }
        if (s0 == q0) {
            int row_lo = q0 + r0l + g, row_hi = row_lo + 8;
            #pragma unroll
            for (int nt = 0; nt < 8; nt++) {
                int col = s0 + nt * 8 + t2;
                if (col     > row_lo) s[nt][0] = -1e30f;
                if (col + 1 > row_lo) s[nt][1] = -1e30f;
                if (col     > row_hi) s[nt][2] = -1e30f;
                if (col + 1 > row_hi) s[nt][3] = -1e30f;
            }
        }
        float rmx_lo = -1e30f, rmx_hi = -1e30f;
        #pragma unroll
        for (int nt = 0; nt < 8; nt++) {
            rmx_lo = fmaxf(rmx_lo, fmaxf(s[nt][0], s[nt][1]));
            rmx_hi = fmaxf(rmx_hi, fmaxf(s[nt][2], s[nt][3]));
        }
        rmx_lo = fmaxf(rmx_lo, __shfl_xor_sync(0xffffffffu, rmx_lo, 1));
        rmx_lo = fmaxf(rmx_lo, __shfl_xor_sync(0xffffffffu, rmx_lo, 2));
        rmx_hi = fmaxf(rmx_hi, __shfl_xor_sync(0xffffffffu, rmx_hi, 1));
        rmx_hi = fmaxf(rmx_hi, __shfl_xor_sync(0xffffffffu, rmx_hi, 2));
        float mn_lo = fmaxf(m_lo, rmx_lo), mn_hi = fmaxf(m_hi, rmx_hi);
        float corr_lo = __expf(m_lo - mn_lo), corr_hi = __expf(m_hi - mn_hi);
        m_lo = mn_lo; m_hi = mn_hi;
        float rs_lo = 0.f, rs_hi = 0.f;
        #pragma unroll
        for (int nt = 0; nt < 8; nt++) {
            s[nt][0] = __expf(s[nt][0] - m_lo); rs_lo += s[nt][0];
            s[nt][1] = __expf(s[nt][1] - m_lo); rs_lo += s[nt][1];
            s[nt][2] = __expf(s[nt][2] - m_hi); rs_hi += s[nt][2];
            s[nt][3] = __expf(s[nt][3] - m_hi); rs_hi += s[nt][3];
        }
        rs_lo += __shfl_xor_sync(0xffffffffu, rs_lo, 1);
        rs_lo += __shfl_xor_sync(0xffffffffu, rs_lo, 2);
        rs_hi += __shfl_xor_sync(0xffffffffu, rs_hi, 1);
        rs_hi += __shfl_xor_sync(0xffffffffu, rs_hi, 2);
        l_lo = l_lo * corr_lo + rs_lo;
        l_hi = l_hi * corr_hi + rs_hi;
        #pragma unroll
        for (int nt = 0; nt < 8; nt++) {
            o[nt][0] *= corr_lo; o[nt][1] *= corr_lo;
            o[nt][2] *= corr_hi; o[nt][3] *= corr_hi;
        }
        uint32_t pf[4][4];
        #pragma unroll
        for (int kk = 0; kk < 4; kk++) {
            __half2 h0 = __floats2half2_rn(s[2*kk][0],   s[2*kk][1]);
            __half2 h1 = __floats2half2_rn(s[2*kk][2],   s[2*kk][3]);
            __half2 h2 = __floats2half2_rn(s[2*kk+1][0], s[2*kk+1][1]);
            __half2 h3 = __floats2half2_rn(s[2*kk+1][2], s[2*kk+1][3]);
            pf[kk][0] = *(uint32_t*)&h0; pf[kk][1] = *(uint32_t*)&h1;
            pf[kk][2] = *(uint32_t*)&h2; pf[kk][3] = *(uint32_t*)&h3;
        }
        #pragma unroll
        for (int ntp = 0; ntp < 4; ntp++) {
            #pragma unroll
            for (int kk = 0; kk < 4; kk++) {
                uint32_t bb[4];
                uint32_t addr = vsb +
                    (((kk * 16 + laneRowV) * AS + ntp * 16 + laneColV) << 1);
                asm volatile(
                    "ldmatrix.sync.aligned.m8n8.x4.trans.shared.b16 {%0,%1,%2,%3}, [%4];"
                    : "=r"(bb[0]), "=r"(bb[1]), "=r"(bb[2]), "=r"(bb[3])
                    : "r"(addr));
                #pragma unroll
                for (int hf = 0; hf < 2; hf++) {
                    int nt = ntp * 2 + hf;
                    asm volatile(
                        "mma.sync.aligned.m16n8k16.row.col.f32.f16.f16.f32 "
                        "{%0,%1,%2,%3}, {%4,%5,%6,%7}, {%8,%9}, {%0,%1,%2,%3};"
                        : "+f"(o[nt][0]), "+f"(o[nt][1]), "+f"(o[nt][2]), "+f"(o[nt][3])
                        : "r"(pf[kk][0]), "r"(pf[kk][1]), "r"(pf[kk][2]), "r"(pf[kk][3]),
                          "r"(bb[hf * 2]), "r"(bb[hf * 2 + 1]));
                }
            }
        }
        __syncthreads();
    }

    float inv_lo = 1.f / l_lo, inv_hi = 1.f / l_hi;
    int row_lo = b * Tt + q0 + r0l + g;
    #pragma unroll
    for (int nt = 0; nt < 8; nt++) {
        int c = h * Dd + nt * 8 + t2;
        __half2 olo = __floats2half2_rn(o[nt][0] * inv_lo, o[nt][1] * inv_lo);
        __half2 ohi = __floats2half2_rn(o[nt][2] * inv_hi, o[nt][3] * inv_hi);
        *(__half2*)(Y + (size_t)row_lo * Cc + c)       = olo;
        *(__half2*)(Y + (size_t)(row_lo + 8) * Cc + c) = ohi;
    }
}

// ---------------- Router + top-2 gating + dispatch lists ---------------------
__global__ __launch_bounds__(128)
void router_k(const float* __restrict__ X, const float* __restrict__ R)
{
    __shared__ float red[128][8];
    int t = blockIdx.x, tid = threadIdx.x;
    const float* xr = X + (size_t)t * Cc;
    float acc[8];
    #pragma unroll
    for (int e = 0; e < 8; e++) acc[e] = 0.f;
    for (int c = tid; c < Cc; c += 128) {
        float xv = xr[c];
        const float* rr = R + c * 8;
        #pragma unroll
        for (int e = 0; e < 8; e++) acc[e] += xv * rr[e];
    }
    #pragma unroll
    for (int e = 0; e < 8; e++) red[tid][e] = acc[e];
    __syncthreads();
    for (int st = 64; st > 0; st >>= 1) {
        if (tid < st)
            #pragma unroll
            for (int e = 0; e < 8; e++) red[tid][e] += red[tid + st][e];
        __syncthreads();
    }
    if (tid == 0) {
        float lg[8];
        #pragma unroll
        for (int e = 0; e < 8; e++) lg[e] = red[0][e];
        int i0 = 0;
        #pragma unroll
        for (int e = 1; e < 8; e++) if (lg[e] > lg[i0]) i0 = e;
        int i1 = (i0 == 0) ? 1 : 0;
        #pragma unroll
        for (int e = 0; e < 8; e++) if (e != i0 && lg[e] > lg[i1]) i1 = e;
        float b2  = expf(lg[i1] - lg[i0]);
        float inv = 1.f / (1.f + b2);
        int p0 = atomicAdd(&g_cnt[i0], 1);
        g_listA[i0 * Tt + p0] = t;
        g_glA [i0 * Tt + p0] = inv;
        int p1 = atomicAdd(&g_cnt[8 + i1], 1);
        g_listA[(8 + i1) * Tt + p1] = t;
        g_glA [(8 + i1) * Tt + p1] = b2 * inv;
    }
}

// ---------------- MoE adapter: 16 tokens x 4 batch = 64 rows per block -------
__global__ __launch_bounds__(256)
void adapter_moe(const float* __restrict__ X, const float* __restrict__ AD_W,
                 const float* __restrict__ AD_B, const float* __restrict__ AU_W,
                 const float* __restrict__ AU_B,
                 float* __restrict__ Y0, float* __restrict__ Y1)
{
    int e = blockIdx.y, kk = blockIdx.z, tile = blockIdx.x;
    int cnt = g_cnt[kk * 8 + e];
    int base = tile * TPB;
    if (base >= cnt) return;
    float* __restrict__ YAD = kk ? Y1 : Y0;

    __shared__ int   ts[TPB];
    __shared__ float gs[TPB];
    __shared__ union {
        float4 W4[64][17];
        float4 AU4[64][16];
    } u;
    __shared__ float down_s[64][65];

    int tid = threadIdx.x;
    if (tid < TPB) {
        int idx = min(base + tid, cnt - 1);
        ts[tid] = g_listA[(kk * 8 + e) * Tt + idx];
        gs[tid] = g_glA [(kk * 8 + e) * Tt + idx];
    }
    __syncthreads();

    int ri = tid >> 2, tq = tid & 3;
    int ti = ri >> 2, b = ri & 3;
    int t  = ts[ti];
    bool active = (base + ti) < cnt;
    size_t xoff = ((size_t)b * Tt + t) * Cc;
    const float* xrowp = X + xoff;
    float gate01 = gs[ti] * 0.1f;

    float acc[16];
    #pragma unroll
    for (int j = 0; j < 16; j++) acc[j] = 0.f;

    for (int cb = 0; cb < 16; cb++) {
        const float4* wsrc = (const float4*)(AD_W + ((size_t)e * Cc + cb * 64) * BOTd);
        #pragma unroll
        for (int i = 0; i < 4; i++) {
            int f = tid + i * 256;
            u.W4[f >> 4][f & 15] = wsrc[f];
        }
        __syncthreads();
        #pragma unroll 4
        for (int cq = 0; cq < 16; cq++) {
            float4 xv = __ldg((const float4*)(xrowp + cb * 64 + cq * 4));
            #pragma unroll
            for (int cc = 0; cc < 4; cc++) {
                float x = (&xv.x)[cc];
                #pragma unroll
                for (int i = 0; i < 4; i++) {
                    float4 w = u.W4[cq * 4 + cc][tq + 4 * i];
                    acc[i*4+0] += x * w.x; acc[i*4+1] += x * w.y;
                    acc[i*4+2] += x * w.z; acc[i*4+3] += x * w.w;
                }
            }
        }
        __syncthreads();
    }
    #pragma unroll
    for (int i = 0; i < 4; i++) {
        int jq = tq + 4 * i;
        #pragma unroll
        for (int m = 0; m < 4; m++) {
            int j = jq * 4 + m;
            down_s[ri][j] = fmaxf(acc[i*4+m] + AD_B[e * BOTd + j], 0.f);
        }
    }
    __syncthreads();

    for (int nb = 0; nb < 16; nb++) {
        #pragma unroll
        for (int i = 0; i < 4; i++) {
            int f = tid + i * 256;
            int j = f >> 4, cq2 = f & 15;
            u.AU4[j][cq2] = *(const float4*)(AU_W + (size_t)e * BOTd * Cc
                                             + (size_t)j * Cc + nb * 64 + cq2 * 4);
        }
        __syncthreads();
        float4 v0 = {0,0,0,0}, v1 = {0,0,0,0}, v2 = {0,0,0,0}, v3 = {0,0,0,0};
        #pragma unroll 8
        for (int j = 0; j < 64; j++) {
            float dv = down_s[ri][j];
            float4 a0 = u.AU4[j][tq];
            float4 a1 = u.AU4[j][tq + 4];
            float4 a2 = u.AU4[j][tq + 8];
            float4 a3 = u.AU4[j][tq + 12];
            v0.x += dv*a0.x; v0.y += dv*a0.y; v0.z += dv*a0.z; v0.w += dv*a0.w;
            v1.x += dv*a1.x; v1.y += dv*a1.y; v1.z += dv*a1.z; v1.w += dv*a1.w;
            v2.x += dv*a2.x; v2.y += dv*a2.y; v2.z += dv*a2.z; v2.w += dv*a2.w;
            v3.x += dv*a3.x; v3.y += dv*a3.y; v3.z += dv*a3.z; v3.w += dv*a3.w;
        }
        if (active) {
            float4 vv[4] = {v0, v1, v2, v3};
            #pragma unroll
            for (int i = 0; i < 4; i++) {
                int col = nb * 64 + (tq + 4 * i) * 4;
                float4 bb = *(const float4*)(AU_B + e * Cc + col);
                float4 o;
                o.x = (vv[i].x + bb.x) * gate01;
                o.y = (vv[i].y + bb.y) * gate01;
                o.z = (vv[i].z + bb.z) * gate01;
                o.w = (vv[i].w + bb.w) * gate01;
                *(float4*)(YAD + xoff + col) = o;
            }
        }
        __syncthreads();
    }
}

// ---------------- launch ----------------------------------------------------
extern "C" void kernel_launch(void* const* d_in, const int* in_sizes, int n_in,
                              void* d_out, int out_size)
{
    const float* x      = (const float*)d_in[0];
    const float* Wq     = (const float*)d_in[1];
    const float* bq     = (const float*)d_in[2];
    const float* Wk     = (const float*)d_in[3];
    const float* bk     = (const float*)d_in[4];
    const float* Wv     = (const float*)d_in[5];
    const float* bv     = (const float*)d_in[6];
    const float* Wo     = (const float*)d_in[7];
    const float* bo     = (const float*)d_in[8];
    const float* ln1_g  = (const float*)d_in[9];
    const float* ln1_b  = (const float*)d_in[10];
    const float* ln2_g  = (const float*)d_in[11];
    const float* ln2_b  = (const float*)d_in[12];
    const float* mlp_w1 = (const float*)d_in[13];
    const float* mlp_b1 = (const float*)d_in[14];
    const float* mlp_w2 = (const float*)d_in[15];
    const float* mlp_b2 = (const float*)d_in[16];
    const float* router = (const float*)d_in[17];
    const float* ad_w   = (const float*)d_in[18];
    const float* ad_b   = (const float*)d_in[19];
    const float* au_w   = (const float*)d_in[20];
    const float* au_b   = (const float*)d_in[21];

    __half *h, *qkv, *y, *h2, *mid, *wqkvt, *wot, *w1t, *w2t;
    float *x1, *yad0, *yad1, *bqkv;
    int *cnt;
    cudaGetSymbolAddress((void**)&h,    g_h);
    cudaGetSymbolAddress((void**)&qkv,  g_qkv);
    cudaGetSymbolAddress((void**)&y,    g_y);
    cudaGetSymbolAddress((void**)&x1,   g_x1);
    cudaGetSymbolAddress((void**)&yad0, g_yad0);
    cudaGetSymbolAddress((void**)&yad1, g_yad1);
    cudaGetSymbolAddress((void**)&h2,   g_h2);
    cudaGetSymbolAddress((void**)&mid,  g_mid);
    cudaGetSymbolAddress((void**)&bqkv, g_bqkv);
    cudaGetSymbolAddress((void**)&cnt,  g_cnt);
    cudaGetSymbolAddress((void**)&wqkvt, g_wqkvt);
    cudaGetSymbolAddress((void**)&wot, g_wot);
    cudaGetSymbolAddress((void**)&w1t, g_w1t);
    cudaGetSymbolAddress((void**)&w2t, g_w2t);

    // opt-in dynamic smem for the 3-stage GEMM (idempotent; first call happens
    // in the pre-capture correctness run)
    cudaFuncSetAttribute(mma_gemm<0, __half>, cudaFuncAttributeMaxDynamicSharedMemorySize, SMEM_GEMM);
    cudaFuncSetAttribute(mma_gemm<1, float>,  cudaFuncAttributeMaxDynamicSharedMemorySize, SMEM_GEMM);
    cudaFuncSetAttribute(mma_gemm<2, __half>, cudaFuncAttributeMaxDynamicSharedMemorySize, SMEM_GEMM);
    cudaFuncSetAttribute(mma_gemm<3, float>,  cudaFuncAttributeMaxDynamicSharedMemorySize, SMEM_GEMM);

    float* out = (float*)d_out;
    dim3 tb(32, 8);
    dim3 gQKV(C3 / 128, Mrows / 128);    // (24, 32)
    dim3 gProj(Cc / 128, Mrows / 128);   // (8, 32)
    dim3 gMlp1(CH / 128, Mrows / 128);   // (32, 32)

    concat_bias<<<3, 256>>>(bq, bk, bv, bqkv);
    transpose_k<<<dim3(Cc/32, Cc/32), tb>>>(Wq, wqkvt, Cc, Cc);
    transpose_k<<<dim3(Cc/32, Cc/32), tb>>>(Wk, wqkvt + (size_t)Cc*Cc, Cc, Cc);
    transpose_k<<<dim3(Cc/32, Cc/32), tb>>>(Wv, wqkvt + (size_t)2*Cc*Cc, Cc, Cc);
    ln_k<<<Mrows, 256>>>(x, ln1_g, ln1_b, h);
    mma_gemm<0, __half><<<gQKV, 256, SMEM_GEMM>>>(h, wqkvt, bqkv, nullptr, nullptr, nullptr,
                                                  qkv, Mrows, C3, Cc);
    transpose_k<<<dim3(Cc/32, Cc/32), tb>>>(Wo, wot, Cc, Cc);
    attn_mma<<<dim3(Tt / 64, Bb * Hh), 128>>>(qkv, y);
    mma_gemm<1, float><<<gProj, 256, SMEM_GEMM>>>(y, wot, bo, x, nullptr, nullptr,
                                                  x1, Mrows, Cc, Cc);
    cudaMemsetAsync(cnt, 0, 16 * sizeof(int));
    router_k<<<Tt, 128>>>(x1, router);
    adapter_moe<<<dim3(Tt / TPB, Ee, 2), 256>>>(x1, ad_w, ad_b, au_w, au_b, yad0, yad1);
    ln_k<<<Mrows, 256>>>(x1, ln2_g, ln2_b, h2);
    transpose_k<<<dim3(CH/32, Cc/32), tb>>>(mlp_w1, w1t, Cc, CH);
    mma_gemm<2, __half><<<gMlp1, 256, SMEM_GEMM>>>(h2, w1t, mlp_b1, nullptr, nullptr, nullptr,
                                                   mid, Mrows, CH, Cc);
    transpose_k<<<dim3(Cc/32, CH/32), tb>>>(mlp_w2, w2t, CH, Cc);
    mma_gemm<3, float><<<gProj, 256, SMEM_GEMM>>>(mid, w2t, mlp_b2, x1, yad0, yad1,
                                                  out, Mrows, Cc, CH);
}

// round 17
// speedup vs baseline: 1.0405x; 1.0405x over previous
#include <cuda_runtime.h>
#include <cuda_fp16.h>
#include <math.h>
#include <stdint.h>

// Problem constants
#define Bb   4
#define Tt   1024
#define Cc   1024
#define Hh   16
#define Dd   64
#define Ee   8
#define BOTd 64
#define Mrows 4096           // B*T
#define CH    4096           // 4*C
#define C3   3072            // 3*C
#define TPB  16              // tokens per adapter block

// ---------------- scratch (device globals; no allocation allowed) -----------
__device__ __half g_h  [Mrows*Cc];
__device__ __half g_qkv[Mrows*C3];
__device__ __half g_y  [Mrows*Cc];
__device__ float  g_x1 [Mrows*Cc];
__device__ float  g_yad0[Mrows*Cc];
__device__ float  g_yad1[Mrows*Cc];
__device__ __half g_h2 [Mrows*Cc];
__device__ __half g_mid[Mrows*CH];
__device__ float  g_bqkv[C3];
// MoE dispatch lists
__device__ int   g_cnt[16];
__device__ int   g_listA[2*Ee*Tt];
__device__ float g_glA [2*Ee*Tt];
// transposed weights, fp16 (K-major B operands: Wt[N][K])
__device__ __half g_wqkvt[C3*Cc];
__device__ __half g_wot[Cc*Cc];
__device__ __half g_w1t[Cc*CH];
__device__ __half g_w2t[CH*Cc];

__device__ __forceinline__ uint32_t s2u(const void* p) {
    return (uint32_t)__cvta_generic_to_shared(p);
}

// ---------------- bias concat: bqkv = [bq | bk | bv] -------------------------
__global__ __launch_bounds__(256)
void concat_bias(const float* __restrict__ bq, const float* __restrict__ bk,
                 const float* __restrict__ bv, float* __restrict__ out)
{
    int b = blockIdx.x;
    const float* src = (b == 0) ? bq : (b == 1) ? bk : bv;
    int i = threadIdx.x * 4;
    *(float4*)(out + b * Cc + i) = *(const float4*)(src + i);
}

// ---------------- FP16 mma.sync GEMM (R15 v3: 2-stage, static smem) ----------
#define SH 40   // smem row stride in halves (80B)

template<int EPI, typename OutT>
__global__ __launch_bounds__(256, 2)
void mma_gemm(const __half* __restrict__ A, const __half* __restrict__ Wt,
              const float* __restrict__ bias, const float* __restrict__ R1,
              const float* __restrict__ R2, const float* __restrict__ R3,
              OutT* __restrict__ O, int Md, int Nd, int Kd)
{
    __shared__ __half As[2][128 * SH];
    __shared__ __half Bs[2][128 * SH];
    int tid = threadIdx.x, wid = tid >> 5, lane = tid & 31;
    int wm = wid & 3, wn = wid >> 2;
    int n0 = blockIdx.x * 128, m0 = blockIdx.y * 128;

    float d[2][8][4];
    #pragma unroll
    for (int mt = 0; mt < 2; mt++)
        #pragma unroll
        for (int nt = 0; nt < 8; nt++)
            #pragma unroll
            for (int r = 0; r < 4; r++) d[mt][nt][r] = 0.f;

    int laneRowA = (lane & 7) + ((lane >> 3) & 1) * 8;
    int laneColA = (lane >> 4) * 8;
    int laneRowB = (lane & 7) + (lane >> 4) * 8;
    int laneColB = ((lane >> 3) & 1) * 8;

    uint32_t asb[2] = { s2u(&As[0][0]), s2u(&As[1][0]) };
    uint32_t bsb[2] = { s2u(&Bs[0][0]), s2u(&Bs[1][0]) };

    const int NC = Kd >> 5;

    #pragma unroll
    for (int l = 0; l < 2; l++) {
        int f = tid + (l << 8);
        int row = f >> 2, c8 = (f & 3) << 3;
        uint32_t da = asb[0] + (((row * SH + c8)) << 1);
        const __half* sa = A + (size_t)(m0 + row) * Kd + c8;
        asm volatile("cp.async.cg.shared.global [%0], [%1], 16;" :: "r"(da), "l"(sa));
        uint32_t db = bsb[0] + (((row * SH + c8)) << 1);
        const __half* sb = Wt + (size_t)(n0 + row) * Kd + c8;
        asm volatile("cp.async.cg.shared.global [%0], [%1], 16;" :: "r"(db), "l"(sb));
    }
    asm volatile("cp.async.commit_group;");
    asm volatile("cp.async.wait_group 0;");
    __syncthreads();

    for (int i = 0; i < NC; i++) {
        int cur = i & 1, nxt = cur ^ 1;
        if (i + 1 < NC) {
            int k0 = (i + 1) << 5;
            #pragma unroll
            for (int l = 0; l < 2; l++) {
                int f = tid + (l << 8);
                int row = f >> 2, c8 = (f & 3) << 3;
                uint32_t da = asb[nxt] + (((row * SH + c8)) << 1);
                const __half* sa = A + (size_t)(m0 + row) * Kd + k0 + c8;
                asm volatile("cp.async.cg.shared.global [%0], [%1], 16;" :: "r"(da), "l"(sa));
                uint32_t db = bsb[nxt] + (((row * SH + c8)) << 1);
                const __half* sb = Wt + (size_t)(n0 + row) * Kd + k0 + c8;
                asm volatile("cp.async.cg.shared.global [%0], [%1], 16;" :: "r"(db), "l"(sb));
            }
            asm volatile("cp.async.commit_group;");
        }
        #pragma unroll
        for (int kk = 0; kk < 2; kk++) {
            int kc = kk << 4;
            uint32_t a[2][4];
            #pragma unroll
            for (int mt = 0; mt < 2; mt++) {
                uint32_t addr = asb[cur] +
                    (((wm * 32 + mt * 16 + laneRowA) * SH + kc + laneColA) << 1);
                asm volatile(
                    "ldmatrix.sync.aligned.m8n8.x4.shared.b16 {%0,%1,%2,%3}, [%4];"
                    : "=r"(a[mt][0]), "=r"(a[mt][1]), "=r"(a[mt][2]), "=r"(a[mt][3])
                    : "r"(addr));
            }
            #pragma unroll
            for (int ntp = 0; ntp < 4; ntp++) {
                uint32_t bb[4];
                uint32_t addr = bsb[cur] +
                    (((wn * 64 + ntp * 16 + laneRowB) * SH + kc + laneColB) << 1);
                asm volatile(
                    "ldmatrix.sync.aligned.m8n8.x4.shared.b16 {%0,%1,%2,%3}, [%4];"
                    : "=r"(bb[0]), "=r"(bb[1]), "=r"(bb[2]), "=r"(bb[3])
                    : "r"(addr));
                #pragma unroll
                for (int hf = 0; hf < 2; hf++) {
                    int nt = ntp * 2 + hf;
                    #pragma unroll
                    for (int mt = 0; mt < 2; mt++) {
                        asm volatile(
                            "mma.sync.aligned.m16n8k16.row.col.f32.f16.f16.f32 "
                            "{%0,%1,%2,%3}, {%4,%5,%6,%7}, {%8,%9}, {%0,%1,%2,%3};"
                            : "+f"(d[mt][nt][0]), "+f"(d[mt][nt][1]),
                              "+f"(d[mt][nt][2]), "+f"(d[mt][nt][3])
                            : "r"(a[mt][0]), "r"(a[mt][1]), "r"(a[mt][2]), "r"(a[mt][3]),
                              "r"(bb[hf * 2]), "r"(bb[hf * 2 + 1]));
                    }
                }
            }
        }
        if (i + 1 < NC) {
            asm volatile("cp.async.wait_group 0;");
            __syncthreads();
        }
    }

    int g = lane >> 2, t2 = (lane & 3) * 2;
    #pragma unroll
    for (int mt = 0; mt < 2; mt++) {
        int r0 = m0 + wm * 32 + mt * 16 + g;
        #pragma unroll
        for (int nt = 0; nt < 8; nt++) {
            int c = n0 + wn * 64 + nt * 8 + t2;
            float bx = bias[c], by = bias[c + 1];
            #pragma unroll
            for (int hrow = 0; hrow < 2; hrow++) {
                int r = r0 + hrow * 8;
                size_t base = (size_t)r * Nd + c;
                float vx = d[mt][nt][hrow * 2]     + bx;
                float vy = d[mt][nt][hrow * 2 + 1] + by;
                if (EPI == 1) {
                    float2 r1 = *(const float2*)(R1 + base);
                    vx += r1.x; vy += r1.y;
                }
                if (EPI == 2) {
                    vx = 0.5f * vx * (1.f + erff(vx * 0.70710678118654752f));
                    vy = 0.5f * vy * (1.f + erff(vy * 0.70710678118654752f));
                }
                if (EPI == 3) {
                    float2 r1 = *(const float2*)(R1 + base);
                    float2 r2 = *(const float2*)(R2 + base);
                    float2 r3 = *(const float2*)(R3 + base);
                    vx += r1.x + r2.x + r3.x; vy += r1.y + r2.y + r3.y;
                }
                if constexpr (sizeof(OutT) == 2) {
                    __half2 hv = __floats2half2_rn(vx, vy);
                    *(__half2*)((__half*)O + base) = hv;
                } else {
                    *(float2*)((float*)O + base) = make_float2(vx, vy);
                }
            }
        }
    }
}

// ------------- weight transpose+convert: in[K][N] f32 -> out[N][K] f16 -------
__global__ __launch_bounds__(256)
void transpose_k(const float* __restrict__ in, __half* __restrict__ out,
                 int K, int N)
{
    __shared__ float t[32][33];
    int kb = blockIdx.y * 32, nb = blockIdx.x * 32;
    int x = threadIdx.x, y = threadIdx.y;   // 32 x 8
    #pragma unroll
    for (int dy = 0; dy < 32; dy += 8)
        t[y + dy][x] = in[(size_t)(kb + y + dy) * N + nb + x];
    __syncthreads();
    #pragma unroll
    for (int dy = 0; dy < 32; dy += 8)
        out[(size_t)(nb + y + dy) * K + kb + x] = __float2half(t[x][y + dy]);
}

// ---------------- LayerNorm: fused sum/sumsq, shfl reduction -----------------
__global__ __launch_bounds__(256)
void ln_k(const float* __restrict__ X, const float* __restrict__ G,
          const float* __restrict__ Bt, __half* __restrict__ O)
{
    __shared__ float sm1[8], sm2[8], bcast[2];
    int row = blockIdx.x, tid = threadIdx.x;
    int wid = tid >> 5, lane = tid & 31;
    const float* xr = X + (size_t)row * Cc;
    float4 xv = *(const float4*)(xr + tid * 4);
    float s1 = xv.x + xv.y + xv.z + xv.w;
    float s2 = xv.x*xv.x + xv.y*xv.y + xv.z*xv.z + xv.w*xv.w;
    #pragma unroll
    for (int off = 16; off > 0; off >>= 1) {
        s1 += __shfl_down_sync(0xffffffffu, s1, off);
        s2 += __shfl_down_sync(0xffffffffu, s2, off);
    }
    if (lane == 0) { sm1[wid] = s1; sm2[wid] = s2; }
    __syncthreads();
    if (wid == 0) {
        float t1 = (lane < 8) ? sm1[lane] : 0.f;
        float t2 = (lane < 8) ? sm2[lane] : 0.f;
        #pragma unroll
        for (int off = 4; off > 0; off >>= 1) {
            t1 += __shfl_down_sync(0xffffffffu, t1, off);
            t2 += __shfl_down_sync(0xffffffffu, t2, off);
        }
        if (lane == 0) {
            float mu = t1 * (1.f / 1024.f);
            float var = t2 * (1.f / 1024.f) - mu * mu;
            bcast[0] = mu;
            bcast[1] = rsqrtf(var + 1e-5f);
        }
    }
    __syncthreads();
    float mu = bcast[0], rs = bcast[1];
    float4 gv = *(const float4*)(G  + tid * 4);
    float4 bv = *(const float4*)(Bt + tid * 4);
    __half2 o0 = __floats2half2_rn((xv.x - mu)*rs*gv.x + bv.x,
                                   (xv.y - mu)*rs*gv.y + bv.y);
    __half2 o1 = __floats2half2_rn((xv.z - mu)*rs*gv.z + bv.z,
                                   (xv.w - mu)*rs*gv.w + bv.w);
    uint2 pk; pk.x = *(uint32_t*)&o0; pk.y = *(uint32_t*)&o1;
    *(uint2*)(O + (size_t)row * Cc + tid * 4) = pk;
}

// ---------------- FP16 tensor-core causal flash attention --------------------
#define AS 72
__global__ __launch_bounds__(128)
void attn_mma(const __half* __restrict__ QKV, __half* __restrict__ Y)
{
    __shared__ __half Ks[64 * AS];
    __shared__ __half Vs[64 * AS];
    int bh = blockIdx.y;
    int b = bh >> 4, h = bh & 15;
    int bx = blockIdx.x;
    int q0 = bx * 64;
    int tid = threadIdx.x, wid = tid >> 5, lane = tid & 31;
    int g = lane >> 2, t2 = (lane & 3) << 1;
    int r0l = wid * 16;

    const __half2 qscale = __floats2half2_rn(0.125f, 0.125f);

    #pragma unroll
    for (int i = 0; i < 4; i++) {
        int f = tid + (i << 7);
        int row = f >> 3, c8 = (f & 7) << 3;
        uint4 v4 = *(const uint4*)(QKV + ((size_t)(b * Tt + q0 + row)) * C3 + h * Dd + c8);
        __half2* hp = (__half2*)&v4;
        hp[0] = __hmul2(hp[0], qscale); hp[1] = __hmul2(hp[1], qscale);
        hp[2] = __hmul2(hp[2], qscale); hp[3] = __hmul2(hp[3], qscale);
        *(uint4*)&Ks[row * AS + c8] = v4;
    }
    __syncthreads();
    uint32_t qf[4][4];
    #pragma unroll
    for (int kk = 0; kk < 4; kk++) {
        qf[kk][0] = *(const uint32_t*)&Ks[(r0l + g) * AS + kk * 16 + t2];
        qf[kk][1] = *(const uint32_t*)&Ks[(r0l + g + 8) * AS + kk * 16 + t2];
        qf[kk][2] = *(const uint32_t*)&Ks[(r0l + g) * AS + kk * 16 + 8 + t2];
        qf[kk][3] = *(const uint32_t*)&Ks[(r0l + g + 8) * AS + kk * 16 + 8 + t2];
    }
    __syncthreads();

    int laneRowV = (lane & 7) + ((lane >> 3) & 1) * 8;
    int laneColV = (lane >> 4) * 8;
    uint32_t vsb = s2u(Vs);

    float m_lo = -1e30f, m_hi = -1e30f, l_lo = 0.f, l_hi = 0.f;
    float o[8][4];
    #pragma unroll
    for (int nt = 0; nt < 8; nt++)
        #pragma unroll
        for (int r = 0; r < 4; r++) o[nt][r] = 0.f;

    for (int it = 0; it <= bx; it++) {
        int s0 = it * 64;
        #pragma unroll
        for (int i = 0; i < 4; i++) {
            int f = tid + (i << 7);
            int row = f >> 3, c8 = (f & 7) << 3;
            size_t rb = ((size_t)(b * Tt + s0 + row)) * C3 + h * Dd + c8;
            *(uint4*)&Ks[row * AS + c8] = *(const uint4*)(QKV + Cc + rb);
            *(uint4*)&Vs[row * AS + c8] = *(const uint4*)(QKV + 2 * Cc + rb);
        }
        __syncthreads();

        float s[8][4];
        #pragma unroll
        for (int nt = 0; nt < 8; nt++) {
            #pragma unroll
            for (int r = 0; r < 4; r++) s[nt][r] = 0.f;
            int n = nt * 8 + g;
            #pragma unroll
            for (int kk = 0; kk < 4; kk++) {
                uint32_t b0 = *(const uint32_t*)&Ks[n * AS + kk * 16 + t2];
                uint32_t b1 = *(const uint32_t*)&Ks[n * AS + kk * 16 + 8 + t2];
                asm volatile(
                    "mma.sync.aligned.m16n8k16.row.col.f32.f16.f16.f32 "
                    "{%0,%1,%2,%3}, {%4,%5,%6,%7}, {%8,%9}, {%0,%1,%2,%3};"
                    : "+f"(s[nt][0]), "+f"(s[nt][1]), "+f"(s[nt][2]), "+f"(s[nt][3])
                    : "r"(qf[kk][0]), "r"(qf[kk][1]), "r"(qf[kk][2]), "r"(qf[kk][3]),
                      "r"(b0), "r"(b1));
            }
        }
        if (s0 == q0) {
            int row_lo = q0 + r0l + g, row_hi = row_lo + 8;
            #pragma unroll
            for (int nt = 0; nt < 8; nt++) {
                int col = s0 + nt * 8 + t2;
                if (col     > row_lo) s[nt][0] = -1e30f;
                if (col + 1 > row_lo) s[nt][1] = -1e30f;
                if (col     > row_hi) s[nt][2] = -1e30f;
                if (col + 1 > row_hi) s[nt][3] = -1e30f;
            }
        }
        float rmx_lo = -1e30f, rmx_hi = -1e30f;
        #pragma unroll
        for (int nt = 0; nt < 8; nt++) {
            rmx_lo = fmaxf(rmx_lo, fmaxf(s[nt][0], s[nt][1]));
            rmx_hi = fmaxf(rmx_hi, fmaxf(s[nt][2], s[nt][3]));
        }
        rmx_lo = fmaxf(rmx_lo, __shfl_xor_sync(0xffffffffu, rmx_lo, 1));
        rmx_lo = fmaxf(rmx_lo, __shfl_xor_sync(0xffffffffu, rmx_lo, 2));
        rmx_hi = fmaxf(rmx_hi, __shfl_xor_sync(0xffffffffu, rmx_hi, 1));
        rmx_hi = fmaxf(rmx_hi, __shfl_xor_sync(0xffffffffu, rmx_hi, 2));
        float mn_lo = fmaxf(m_lo, rmx_lo), mn_hi = fmaxf(m_hi, rmx_hi);
        float corr_lo = __expf(m_lo - mn_lo), corr_hi = __expf(m_hi - mn_hi);
        m_lo = mn_lo; m_hi = mn_hi;
        float rs_lo = 0.f, rs_hi = 0.f;
        #pragma unroll
        for (int nt = 0; nt < 8; nt++) {
            s[nt][0] = __expf(s[nt][0] - m_lo); rs_lo += s[nt][0];
            s[nt][1] = __expf(s[nt][1] - m_lo); rs_lo += s[nt][1];
            s[nt][2] = __expf(s[nt][2] - m_hi); rs_hi += s[nt][2];
            s[nt][3] = __expf(s[nt][3] - m_hi); rs_hi += s[nt][3];
        }
        rs_lo += __shfl_xor_sync(0xffffffffu, rs_lo, 1);
        rs_lo += __shfl_xor_sync(0xffffffffu, rs_lo, 2);
        rs_hi += __shfl_xor_sync(0xffffffffu, rs_hi, 1);
        rs_hi += __shfl_xor_sync(0xffffffffu, rs_hi, 2);
        l_lo = l_lo * corr_lo + rs_lo;
        l_hi = l_hi * corr_hi + rs_hi;
        #pragma unroll
        for (int nt = 0; nt < 8; nt++) {
            o[nt][0] *= corr_lo; o[nt][1] *= corr_lo;
            o[nt][2] *= corr_hi; o[nt][3] *= corr_hi;
        }
        uint32_t pf[4][4];
        #pragma unroll
        for (int kk = 0; kk < 4; kk++) {
            __half2 h0 = __floats2half2_rn(s[2*kk][0],   s[2*kk][1]);
            __half2 h1 = __floats2half2_rn(s[2*kk][2],   s[2*kk][3]);
            __half2 h2 = __floats2half2_rn(s[2*kk+1][0], s[2*kk+1][1]);
            __half2 h3 = __floats2half2_rn(s[2*kk+1][2], s[2*kk+1][3]);
            pf[kk][0] = *(uint32_t*)&h0; pf[kk][1] = *(uint32_t*)&h1;
            pf[kk][2] = *(uint32_t*)&h2; pf[kk][3] = *(uint32_t*)&h3;
        }
        #pragma unroll
        for (int ntp = 0; ntp < 4; ntp++) {
            #pragma unroll
            for (int kk = 0; kk < 4; kk++) {
                uint32_t bb[4];
                uint32_t addr = vsb +
                    (((kk * 16 + laneRowV) * AS + ntp * 16 + laneColV) << 1);
                asm volatile(
                    "ldmatrix.sync.aligned.m8n8.x4.trans.shared.b16 {%0,%1,%2,%3}, [%4];"
                    : "=r"(bb[0]), "=r"(bb[1]), "=r"(bb[2]), "=r"(bb[3])
                    : "r"(addr));
                #pragma unroll
                for (int hf = 0; hf < 2; hf++) {
                    int nt = ntp * 2 + hf;
                    asm volatile(
                        "mma.sync.aligned.m16n8k16.row.col.f32.f16.f16.f32 "
                        "{%0,%1,%2,%3}, {%4,%5,%6,%7}, {%8,%9}, {%0,%1,%2,%3};"
                        : "+f"(o[nt][0]), "+f"(o[nt][1]), "+f"(o[nt][2]), "+f"(o[nt][3])
                        : "r"(pf[kk][0]), "r"(pf[kk][1]), "r"(pf[kk][2]), "r"(pf[kk][3]),
                          "r"(bb[hf * 2]), "r"(bb[hf * 2 + 1]));
                }
            }
        }
        __syncthreads();
    }

    float inv_lo = 1.f / l_lo, inv_hi = 1.f / l_hi;
    int row_lo = b * Tt + q0 + r0l + g;
    #pragma unroll
    for (int nt = 0; nt < 8; nt++) {
        int c = h * Dd + nt * 8 + t2;
        __half2 olo = __floats2half2_rn(o[nt][0] * inv_lo, o[nt][1] * inv_lo);
        __half2 ohi = __floats2half2_rn(o[nt][2] * inv_hi, o[nt][3] * inv_hi);
        *(__half2*)(Y + (size_t)row_lo * Cc + c)       = olo;
        *(__half2*)(Y + (size_t)(row_lo + 8) * Cc + c) = ohi;
    }
}

// ---------------- Router + top-2 gating + dispatch lists ---------------------
__global__ __launch_bounds__(128)
void router_k(const float* __restrict__ X, const float* __restrict__ R)
{
    __shared__ float red[128][8];
    int t = blockIdx.x, tid = threadIdx.x;
    const float* xr = X + (size_t)t * Cc;
    float acc[8];
    #pragma unroll
    for (int e = 0; e < 8; e++) acc[e] = 0.f;
    for (int c = tid; c < Cc; c += 128) {
        float xv = xr[c];
        const float* rr = R + c * 8;
        #pragma unroll
        for (int e = 0; e < 8; e++) acc[e] += xv * rr[e];
    }
    #pragma unroll
    for (int e = 0; e < 8; e++) red[tid][e] = acc[e];
    __syncthreads();
    for (int st = 64; st > 0; st >>= 1) {
        if (tid < st)
            #pragma unroll
            for (int e = 0; e < 8; e++) red[tid][e] += red[tid + st][e];
        __syncthreads();
    }
    if (tid == 0) {
        float lg[8];
        #pragma unroll
        for (int e = 0; e < 8; e++) lg[e] = red[0][e];
        int i0 = 0;
        #pragma unroll
        for (int e = 1; e < 8; e++) if (lg[e] > lg[i0]) i0 = e;
        int i1 = (i0 == 0) ? 1 : 0;
        #pragma unroll
        for (int e = 0; e < 8; e++) if (e != i0 && lg[e] > lg[i1]) i1 = e;
        float b2  = expf(lg[i1] - lg[i0]);
        float inv = 1.f / (1.f + b2);
        int p0 = atomicAdd(&g_cnt[i0], 1);
        g_listA[i0 * Tt + p0] = t;
        g_glA [i0 * Tt + p0] = inv;
        int p1 = atomicAdd(&g_cnt[8 + i1], 1);
        g_listA[(8 + i1) * Tt + p1] = t;
        g_glA [(8 + i1) * Tt + p1] = b2 * inv;
    }
}

// ---------------- MoE adapter: 16 tokens x 4 batch = 64 rows per block -------
__global__ __launch_bounds__(256)
void adapter_moe(const float* __restrict__ X, const float* __restrict__ AD_W,
                 const float* __restrict__ AD_B, const float* __restrict__ AU_W,
                 const float* __restrict__ AU_B,
                 float* __restrict__ Y0, float* __restrict__ Y1)
{
    int e = blockIdx.y, kk = blockIdx.z, tile = blockIdx.x;
    int cnt = g_cnt[kk * 8 + e];
    int base = tile * TPB;
    if (base >= cnt) return;
    float* __restrict__ YAD = kk ? Y1 : Y0;

    __shared__ int   ts[TPB];
    __shared__ float gs[TPB];
    __shared__ union {
        float4 W4[64][17];
        float4 AU4[64][16];
    } u;
    __shared__ float down_s[64][65];

    int tid = threadIdx.x;
    if (tid < TPB) {
        int idx = min(base + tid, cnt - 1);
        ts[tid] = g_listA[(kk * 8 + e) * Tt + idx];
        gs[tid] = g_glA [(kk * 8 + e) * Tt + idx];
    }
    __syncthreads();

    int ri = tid >> 2, tq = tid & 3;
    int ti = ri >> 2, b = ri & 3;
    int t  = ts[ti];
    bool active = (base + ti) < cnt;
    size_t xoff = ((size_t)b * Tt + t) * Cc;
    const float* xrowp = X + xoff;
    float gate01 = gs[ti] * 0.1f;

    float acc[16];
    #pragma unroll
    for (int j = 0; j < 16; j++) acc[j] = 0.f;

    for (int cb = 0; cb < 16; cb++) {
        const float4* wsrc = (const float4*)(AD_W + ((size_t)e * Cc + cb * 64) * BOTd);
        #pragma unroll
        for (int i = 0; i < 4; i++) {
            int f = tid + i * 256;
            u.W4[f >> 4][f & 15] = wsrc[f];
        }
        __syncthreads();
        #pragma unroll 4
        for (int cq = 0; cq < 16; cq++) {
            float4 xv = __ldg((const float4*)(xrowp + cb * 64 + cq * 4));
            #pragma unroll
            for (int cc = 0; cc < 4; cc++) {
                float x = (&xv.x)[cc];
                #pragma unroll
                for (int i = 0; i < 4; i++) {
                    float4 w = u.W4[cq * 4 + cc][tq + 4 * i];
                    acc[i*4+0] += x * w.x; acc[i*4+1] += x * w.y;
                    acc[i*4+2] += x * w.z; acc[i*4+3] += x * w.w;
                }
            }
        }
        __syncthreads();
    }
    #pragma unroll
    for (int i = 0; i < 4; i++) {
        int jq = tq + 4 * i;
        #pragma unroll
        for (int m = 0; m < 4; m++) {
            int j = jq * 4 + m;
            down_s[ri][j] = fmaxf(acc[i*4+m] + AD_B[e * BOTd + j], 0.f);
        }
    }
    __syncthreads();

    for (int nb = 0; nb < 16; nb++) {
        #pragma unroll
        for (int i = 0; i < 4; i++) {
            int f = tid + i * 256;
            int j = f >> 4, cq2 = f & 15;
            u.AU4[j][cq2] = *(const float4*)(AU_W + (size_t)e * BOTd * Cc
                                             + (size_t)j * Cc + nb * 64 + cq2 * 4);
        }
        __syncthreads();
        float4 v0 = {0,0,0,0}, v1 = {0,0,0,0}, v2 = {0,0,0,0}, v3 = {0,0,0,0};
        #pragma unroll 8
        for (int j = 0; j < 64; j++) {
            float dv = down_s[ri][j];
            float4 a0 = u.AU4[j][tq];
            float4 a1 = u.AU4[j][tq + 4];
            float4 a2 = u.AU4[j][tq + 8];
            float4 a3 = u.AU4[j][tq + 12];
            v0.x += dv*a0.x; v0.y += dv*a0.y; v0.z += dv*a0.z; v0.w += dv*a0.w;
            v1.x += dv*a1.x; v1.y += dv*a1.y; v1.z += dv*a1.z; v1.w += dv*a1.w;
            v2.x += dv*a2.x; v2.y += dv*a2.y; v2.z += dv*a2.z; v2.w += dv*a2.w;
            v3.x += dv*a3.x; v3.y += dv*a3.y; v3.z += dv*a3.z; v3.w += dv*a3.w;
        }
        if (active) {
            float4 vv[4] = {v0, v1, v2, v3};
            #pragma unroll
            for (int i = 0; i < 4; i++) {
                int col = nb * 64 + (tq + 4 * i) * 4;
                float4 bb = *(const float4*)(AU_B + e * Cc + col);
                float4 o;
                o.x = (vv[i].x + bb.x) * gate01;
                o.y = (vv[i].y + bb.y) * gate01;
                o.z = (vv[i].z + bb.z) * gate01;
                o.w = (vv[i].w + bb.w) * gate01;
                *(float4*)(YAD + xoff + col) = o;
            }
        }
        __syncthreads();
    }
}

// ---------------- launch ----------------------------------------------------
static cudaStream_t s_side = nullptr;
static cudaEvent_t  s_e0 = nullptr, s_ew = nullptr, s_e1 = nullptr, s_e2 = nullptr;

extern "C" void kernel_launch(void* const* d_in, const int* in_sizes, int n_in,
                              void* d_out, int out_size)
{
    const float* x      = (const float*)d_in[0];
    const float* Wq     = (const float*)d_in[1];
    const float* bq     = (const float*)d_in[2];
    const float* Wk     = (const float*)d_in[3];
    const float* bk     = (const float*)d_in[4];
    const float* Wv     = (const float*)d_in[5];
    const float* bv     = (const float*)d_in[6];
    const float* Wo     = (const float*)d_in[7];
    const float* bo     = (const float*)d_in[8];
    const float* ln1_g  = (const float*)d_in[9];
    const float* ln1_b  = (const float*)d_in[10];
    const float* ln2_g  = (const float*)d_in[11];
    const float* ln2_b  = (const float*)d_in[12];
    const float* mlp_w1 = (const float*)d_in[13];
    const float* mlp_b1 = (const float*)d_in[14];
    const float* mlp_w2 = (const float*)d_in[15];
    const float* mlp_b2 = (const float*)d_in[16];
    const float* router = (const float*)d_in[17];
    const float* ad_w   = (const float*)d_in[18];
    const float* ad_b   = (const float*)d_in[19];
    const float* au_w   = (const float*)d_in[20];
    const float* au_b   = (const float*)d_in[21];

    __half *h, *qkv, *y, *h2, *mid, *wqkvt, *wot, *w1t, *w2t;
    float *x1, *yad0, *yad1, *bqkv;
    int *cnt;
    cudaGetSymbolAddress((void**)&h,    g_h);
    cudaGetSymbolAddress((void**)&qkv,  g_qkv);
    cudaGetSymbolAddress((void**)&y,    g_y);
    cudaGetSymbolAddress((void**)&x1,   g_x1);
    cudaGetSymbolAddress((void**)&yad0, g_yad0);
    cudaGetSymbolAddress((void**)&yad1, g_yad1);
    cudaGetSymbolAddress((void**)&h2,   g_h2);
    cudaGetSymbolAddress((void**)&mid,  g_mid);
    cudaGetSymbolAddress((void**)&bqkv, g_bqkv);
    cudaGetSymbolAddress((void**)&cnt,  g_cnt);
    cudaGetSymbolAddress((void**)&wqkvt, g_wqkvt);
    cudaGetSymbolAddress((void**)&wot, g_wot);
    cudaGetSymbolAddress((void**)&w1t, g_w1t);
    cudaGetSymbolAddress((void**)&w2t, g_w2t);

    // one-time host-object setup (no device memory involved)
    if (!s_side) {
        cudaStreamCreateWithFlags(&s_side, cudaStreamNonBlocking);
        cudaEventCreateWithFlags(&s_e0, cudaEventDisableTiming);
        cudaEventCreateWithFlags(&s_ew, cudaEventDisableTiming);
        cudaEventCreateWithFlags(&s_e1, cudaEventDisableTiming);
        cudaEventCreateWithFlags(&s_e2, cudaEventDisableTiming);
    }

    float* out = (float*)d_out;
    dim3 tb(32, 8);
    dim3 gQKV(C3 / 128, Mrows / 128);    // (24, 32)
    dim3 gProj(Cc / 128, Mrows / 128);   // (8, 32)
    dim3 gMlp1(CH / 128, Mrows / 128);   // (32, 32)

    // ---- fork side stream into the capture ---------------------------------
    cudaEventRecord(s_e0, 0);
    cudaStreamWaitEvent(s_side, s_e0, 0);

    // side stream: transposes only needed later (Wo, W1, W2)
    transpose_k<<<dim3(Cc/32, Cc/32), tb, 0, s_side>>>(Wo, wot, Cc, Cc);
    transpose_k<<<dim3(CH/32, Cc/32), tb, 0, s_side>>>(mlp_w1, w1t, Cc, CH);
    transpose_k<<<dim3(Cc/32, CH/32), tb, 0, s_side>>>(mlp_w2, w2t, CH, Cc);
    cudaEventRecord(s_ew, s_side);

    // main stream: QKV path
    concat_bias<<<3, 256>>>(bq, bk, bv, bqkv);
    transpose_k<<<dim3(Cc/32, Cc/32), tb>>>(Wq, wqkvt, Cc, Cc);
    transpose_k<<<dim3(Cc/32, Cc/32), tb>>>(Wk, wqkvt + (size_t)Cc*Cc, Cc, Cc);
    transpose_k<<<dim3(Cc/32, Cc/32), tb>>>(Wv, wqkvt + (size_t)2*Cc*Cc, Cc, Cc);
    ln_k<<<Mrows, 256>>>(x, ln1_g, ln1_b, h);
    mma_gemm<0, __half><<<gQKV, 256>>>(h, wqkvt, bqkv, nullptr, nullptr, nullptr,
                                       qkv, Mrows, C3, Cc);
    attn_mma<<<dim3(Tt / 64, Bb * Hh), 128>>>(qkv, y);
    cudaStreamWaitEvent(0, s_ew, 0);    // need wot (also w1t/w2t now ready)
    mma_gemm<1, float><<<gProj, 256>>>(y, wot, bo, x, nullptr, nullptr,
                                       x1, Mrows, Cc, Cc);
    cudaEventRecord(s_e1, 0);

    // side stream: router + adapter (depends only on x1)
    cudaStreamWaitEvent(s_side, s_e1, 0);
    cudaMemsetAsync(cnt, 0, 16 * sizeof(int), s_side);
    router_k<<<Tt, 128, 0, s_side>>>(x1, router);
    adapter_moe<<<dim3(Tt / TPB, Ee, 2), 256, 0, s_side>>>(x1, ad_w, ad_b, au_w, au_b,
                                                           yad0, yad1);
    cudaEventRecord(s_e2, s_side);

    // main stream: MLP path (concurrent with adapter)
    ln_k<<<Mrows, 256>>>(x1, ln2_g, ln2_b, h2);
    mma_gemm<2, __half><<<gMlp1, 256>>>(h2, w1t, mlp_b1, nullptr, nullptr, nullptr,
                                        mid, Mrows, CH, Cc);
    cudaStreamWaitEvent(0, s_e2, 0);    // join: need yad0/yad1
    mma_gemm<3, float><<<gProj, 256>>>(mid, w2t, mlp_b2, x1, yad0, yad1,
                                       out, Mrows, Cc, CH);
}